// round 15
// baseline (speedup 1.0000x reference)
#include <cuda_runtime.h>
#include <cstdint>
#include <math.h>

#define TOKENS 2048
#define DIM    512
#define NEXP   16
#define HID    2048
#define NSLOTS (TOKENS*2)
#define TMT    128
#define KC     32
#define MAXT   48
#define TM2    64
#define MAXT2  80
#define SPLITK 2
#define NB1    (HID/128)   // 16
#define NB2    (DIM/128)   // 4
// gemm1 (cp.async A, permuted layout)
#define ASTR   40
#define BSTR   136
#define ABYTES (128*ASTR*4)              // 20480
#define SBYTES (ABYTES + KC*BSTR*4)      // 37888
#define SFLOAT (SBYTES/4)
#define AFLOAT (ABYTES/4)
// gemm2 (reg A path, natural layout)
#define ASTR2   36
#define ABY2    (64*ASTR2*4)             // 9216
#define BSTAGE  (KC*BSTR*4)              // 17408
#define SMEM2   (2*ABY2 + 3*BSTAGE)      // 70656

// ---------------- device scratch ----------------
__device__ int   g_cnt[NEXP];
__device__ int   g_list[NEXP*TOKENS];
__device__ float g_wk[NSLOTS];
__device__ float g_psum[NSLOTS*NB1], g_psq[NSLOTS*NB1];
__device__ float g_xr[(size_t)TOKENS*DIM];
__device__ float g_hbuf[(size_t)NSLOTS*HID];

// ---------------- helpers ----------------
__device__ __forceinline__ uint32_t smem_u32(const void* p) {
    uint32_t a;
    asm("{ .reg .u64 t; cvta.to.shared.u64 t, %1; cvt.u32.u64 %0, t; }" : "=r"(a) : "l"(p));
    return a;
}
__device__ __forceinline__ uint32_t tf32r(float x) {
    uint32_t r; asm("cvt.rna.tf32.f32 %0, %1;" : "=r"(r) : "f"(x)); return r;
}
__device__ __forceinline__ float tf32f(float x) { return __uint_as_float(tf32r(x)); }
__device__ __forceinline__ void mma8(float* d, const uint32_t* a, const uint32_t* b) {
    asm("mma.sync.aligned.m16n8k8.row.col.f32.tf32.tf32.f32 "
        "{%0,%1,%2,%3}, {%4,%5,%6,%7}, {%8,%9}, {%0,%1,%2,%3};"
        : "+f"(d[0]), "+f"(d[1]), "+f"(d[2]), "+f"(d[3])
        : "r"(a[0]), "r"(a[1]), "r"(a[2]), "r"(a[3]), "r"(b[0]), "r"(b[1]));
}
__device__ __forceinline__ void cpa16(uint32_t dst, const float* src) {
    asm volatile("cp.async.cg.shared.global [%0], [%1], 16;" :: "r"(dst), "l"(src));
}
#define CP_COMMIT() asm volatile("cp.async.commit_group;" ::: "memory")
#define CP_WAIT1()  asm volatile("cp.async.wait_group 1;" ::: "memory")
__device__ __forceinline__ void sts128(uint32_t a, float x, float y, float z, float w) {
    asm volatile("st.shared.v4.f32 [%0], {%1,%2,%3,%4};" :: "r"(a), "f"(x), "f"(y), "f"(z), "f"(w));
}
__device__ __forceinline__ void redadd(float* p, float v) {
    asm volatile("red.global.add.f32 [%0], %1;" :: "l"(p), "f"(v) : "memory");
}
__device__ __forceinline__ float silu(float v) { return v / (1.f + __expf(-v)); }

// tile -> (expert, gp0 global, loc0 within-expert, rows); returns false past end
__device__ __forceinline__ bool tilemap(int tile, int TM, int& e, int& gp0, int& loc0, int& rows) {
    int a = 0, tt = tile;
    bool ok = false;
#pragma unroll
    for (int ee = 0; ee < NEXP; ee++) {
        int c = g_cnt[ee];
        int nt = (c + TM - 1) / TM;
        if (!ok) {
            if (tt < nt) {
                e = ee; loc0 = tt * TM; gp0 = a + loc0;
                rows = min(TM, c - loc0); ok = true;
            } else tt -= nt;
        }
        a += c;
    }
    return ok;
}

// ---------------- route: smem-staged gate GEMV + top-2 + softmax + permuted tf32 x ----------------
__global__ __launch_bounds__(256) void route_kernel(const float* __restrict__ x,
                                                    const float* __restrict__ Wg) {
    __shared__ float sW[DIM * NEXP];   // 32 KB
    int tid = threadIdx.x;
    // cooperative Wg load (float4)
    {
        const float4* Wg4 = (const float4*)Wg;
        float4* sW4 = (float4*)sW;
#pragma unroll
        for (int i = 0; i < DIM * NEXP / 4 / 256; i++)
            sW4[tid + i * 256] = Wg4[tid + i * 256];
    }
    __syncthreads();

    int t = blockIdx.x * 8 + (tid >> 5);
    int lane = tid & 31;
    const float* xr = x + (size_t)t * DIM;
    // lanes 0-15: expert=lane over d[0,256); lanes 16-31: expert=lane-16 over d[256,512)
    int ex = lane & 15;
    int off = (lane >> 4) * 256;
    const float* xh = xr + off;
    float a0 = 0.f, a1 = 0.f, a2 = 0.f, a3 = 0.f;
#pragma unroll 8
    for (int d = 0; d < 256; d += 4) {
        float4 xv = *(const float4*)(xh + d);
        const float* wrow = sW + (off + d) * NEXP + ex;
        a0 = fmaf(xv.x, wrow[0],  a0);
        a1 = fmaf(xv.y, wrow[16], a1);
        a2 = fmaf(xv.z, wrow[32], a2);
        a3 = fmaf(xv.w, wrow[48], a3);
    }
    float acc = (a0 + a1) + (a2 + a3);
    acc += __shfl_down_sync(0xffffffffu, acc, 16);
    float v0 = -1e30f, v1 = -1e30f;
    int i0 = 0, i1 = 0;
#pragma unroll
    for (int i = 0; i < NEXP; i++) {
        float vi = __shfl_sync(0xffffffffu, acc, i);
        if (vi > v0)      { v1 = v0; i1 = i0; v0 = vi; i0 = i; }
        else if (vi > v1) { v1 = vi; i1 = i; }
    }
    if (lane == 0) {
        float e1 = __expf(v1 - v0);
        float s  = 1.f + e1;
        g_wk[t * 2 + 0] = 1.f / s;
        g_wk[t * 2 + 1] = e1 / s;
        int p0 = atomicAdd(&g_cnt[i0], 1);
        g_list[i0 * TOKENS + p0] = t * 2 + 0;
        int p1 = atomicAdd(&g_cnt[i1], 1);
        g_list[i1 * TOKENS + p1] = t * 2 + 1;
    }
    // write permuted tf32 row (8-group perm k0,k4,k1,k5,k2,k6,k3,k7); lane does 2 groups
#pragma unroll
    for (int j = 0; j < 2; j++) {
        int G = lane * 2 + j;
        const float4* s = (const float4*)(xr + G * 8);
        float4 u = s[0], v = s[1];
        float4 o0 = make_float4(tf32f(u.x), tf32f(v.x), tf32f(u.y), tf32f(v.y));
        float4 o1 = make_float4(tf32f(u.z), tf32f(v.z), tf32f(u.w), tf32f(v.w));
        float4* dd = (float4*)(g_xr + (size_t)t * DIM + G * 8);
        dd[0] = o0; dd[1] = o1;
    }
}

// ---------------- GEMM1: h = silu(xr @ W1 + b1), fused LN partials ----------------
__global__ __launch_bounds__(256, 2) void gemm1_kernel(const float* __restrict__ W1,
                                                       const float* __restrict__ b1) {
    extern __shared__ float dsm[];
    __shared__ int s_tok[TMT];
    int e, gp0, loc0, rows;
    if (!tilemap(blockIdx.y, TMT, e, gp0, loc0, rows)) return;
    int n0 = blockIdx.x * 128;
    int tid = threadIdx.x, lane = tid & 31, wid = tid >> 5;
    int g = lane >> 2, tg = lane & 3;
    int wm = wid & 1, wn = wid >> 1;
    uint32_t dynb = smem_u32(dsm);

    if (tid < TMT) {
        int r = (tid < rows) ? tid : rows - 1;
        s_tok[tid] = g_list[e * TOKENS + loc0 + r] >> 1;
    }
    __syncthreads();

    const float* pA[4];
    uint32_t dA[4];
    const float* pB[4];
    uint32_t dB[4];
    const float* Wb = W1 + (size_t)e * DIM * HID + n0;
#pragma unroll
    for (int i = 0; i < 4; i++) {
        int c = tid + 256 * i;
        int row = c >> 3, fo = (c & 7) * 4;
        pA[i] = g_xr + (size_t)s_tok[row] * DIM + fo;
        dA[i] = dynb + (uint32_t)(row * (ASTR * 4) + fo * 4);
        int kr = c >> 5, nc = (c & 31) * 4;
        pB[i] = Wb + (size_t)kr * HID + nc;
        dB[i] = dynb + (uint32_t)(ABYTES + kr * (BSTR * 4) + nc * 4);
    }

    float d[4][4][4];
#pragma unroll
    for (int i = 0; i < 4; i++)
#pragma unroll
        for (int j = 0; j < 4; j++)
#pragma unroll
            for (int c = 0; c < 4; c++) d[i][j][c] = 0.f;

    const int S = DIM / KC;   // 16
#pragma unroll
    for (int ps = 0; ps < 2; ps++) {
#pragma unroll
        for (int i = 0; i < 4; i++) {
            cpa16(dA[i] + ps * SBYTES, pA[i] + ps * KC);
            cpa16(dB[i] + ps * SBYTES, pB[i] + (size_t)ps * KC * HID);
        }
        CP_COMMIT();
    }

    int st = 0, si = 2;
    for (int s = 0; s < S; s++) {
        CP_WAIT1();
        __syncthreads();
        if (s + 2 < S) {
            int k0 = (s + 2) * KC;
#pragma unroll
            for (int i = 0; i < 4; i++) {
                cpa16(dA[i] + si * SBYTES, pA[i] + k0);
                cpa16(dB[i] + si * SBYTES, pB[i] + (size_t)k0 * HID);
            }
        }
        CP_COMMIT();
        const float* Ab = dsm + st * SFLOAT;
        const float* Bb = Ab + AFLOAT;
#pragma unroll
        for (int k8 = 0; k8 < KC; k8 += 8) {
            uint32_t af[4][4], bf[4][2];
#pragma unroll
            for (int mf = 0; mf < 4; mf++) {
                const float* ap = Ab + (wm * 64 + mf * 16 + g) * ASTR + k8 + 2 * tg;
                float2 lo = *(const float2*)ap;
                float2 hi = *(const float2*)(ap + 8 * ASTR);
                af[mf][0] = __float_as_uint(lo.x);
                af[mf][1] = __float_as_uint(hi.x);
                af[mf][2] = __float_as_uint(lo.y);
                af[mf][3] = __float_as_uint(hi.y);
            }
#pragma unroll
            for (int nf = 0; nf < 4; nf++) {
                const float* bp = Bb + (k8 + tg) * BSTR + wn * 32 + nf * 8 + g;
                bf[nf][0] = tf32r(bp[0]);
                bf[nf][1] = tf32r(bp[4 * BSTR]);
            }
#pragma unroll
            for (int mf = 0; mf < 4; mf++)
#pragma unroll
                for (int nf = 0; nf < 4; nf++)
                    mma8(d[mf][nf], af[mf], bf[nf]);
        }
        st = (st == 2) ? 0 : st + 1;
        si = (si == 2) ? 0 : si + 1;
    }
    __syncthreads();
    float* s_sum = dsm;
    float* s_sq  = dsm + 512;

    const float* brow = b1 + (size_t)e * HID + n0;
    float bias[4][2];
#pragma unroll
    for (int nf = 0; nf < 4; nf++) {
        int n = wn * 32 + nf * 8 + tg * 2;
        bias[nf][0] = brow[n];
        bias[nf][1] = brow[n + 1];
    }
#pragma unroll
    for (int mf = 0; mf < 4; mf++) {
#pragma unroll
        for (int h = 0; h < 2; h++) {
            int lr = wm * 64 + mf * 16 + g + 8 * h;
            bool val = (lr < rows);
            int gp = gp0 + lr;
            float ss = 0.f, qq = 0.f;
            float* hrow = g_hbuf + (size_t)gp * HID + n0;
#pragma unroll
            for (int nf = 0; nf < 4; nf++) {
                float v0 = silu(d[mf][nf][2 * h + 0] + bias[nf][0]);
                float v1 = silu(d[mf][nf][2 * h + 1] + bias[nf][1]);
                ss += v0 + v1;
                qq += v0 * v0 + v1 * v1;
                if (val) {
                    *(float2*)(hrow + wn * 32 + nf * 8 + tg * 2) = make_float2(v0, v1);
                }
            }
            ss += __shfl_xor_sync(0xffffffffu, ss, 1);
            ss += __shfl_xor_sync(0xffffffffu, ss, 2);
            qq += __shfl_xor_sync(0xffffffffu, qq, 1);
            qq += __shfl_xor_sync(0xffffffffu, qq, 2);
            if (tg == 0) { s_sum[wn * TMT + lr] = ss; s_sq[wn * TMT + lr] = qq; }
        }
    }
    __syncthreads();
    if (tid < TMT && tid < rows) {
        float ts = s_sum[tid] + s_sum[TMT + tid] + s_sum[2 * TMT + tid] + s_sum[3 * TMT + tid];
        float tq = s_sq[tid] + s_sq[TMT + tid] + s_sq[2 * TMT + tid] + s_sq[3 * TMT + tid];
        g_psum[(size_t)(gp0 + tid) * NB1 + blockIdx.x] = ts;
        g_psq [(size_t)(gp0 + tid) * NB1 + blockIdx.x] = tq;
    }
}

// ---------------- GEMM2 (TM=64, split-K=2): out += w * ((LN(h)g+b) @ W2 [+ b2]) ----------------
__global__ __launch_bounds__(256, 2) void gemm2_kernel(const float* __restrict__ W2,
                                                       const float* __restrict__ b2,
                                                       const float* __restrict__ ln_g,
                                                       const float* __restrict__ ln_b,
                                                       float* __restrict__ out) {
    extern __shared__ float dsm[];
    __shared__ int s_gp[TM2], s_slot[TM2];
    __shared__ float s_w[TM2], s_mu[TM2], s_rs[TM2];
    __shared__ float s_red[512];
    int e, gp0, loc0, rows;
    if (!tilemap(blockIdx.y, TM2, e, gp0, loc0, rows)) return;
    int n0 = blockIdx.x * 128;
    int ks = blockIdx.z;
    int kbase = ks * (HID / SPLITK);
    int tid = threadIdx.x, lane = tid & 31, wid = tid >> 5;
    int g = lane >> 2, tg = lane & 3;
    int wm = wid & 1, wn = wid >> 1;
    uint32_t dynb = smem_u32(dsm);

    // inline LN stats
    {
        int row = tid >> 2, part = tid & 3;
        int r = (row < rows) ? row : rows - 1;
        int gp = gp0 + r;
        const float* pp = g_psum + (size_t)gp * NB1 + part * 4;
        const float* qp = g_psq  + (size_t)gp * NB1 + part * 4;
        s_red[tid] = pp[0] + pp[1] + pp[2] + pp[3];
        s_red[256 + tid] = qp[0] + qp[1] + qp[2] + qp[3];
    }
    __syncthreads();
    if (tid < TM2) {
        float ps = s_red[tid * 4] + s_red[tid * 4 + 1] + s_red[tid * 4 + 2] + s_red[tid * 4 + 3];
        float qs = s_red[256 + tid * 4] + s_red[256 + tid * 4 + 1] +
                   s_red[256 + tid * 4 + 2] + s_red[256 + tid * 4 + 3];
        float mu = ps * (1.f / HID);
        float var = qs * (1.f / HID) - mu * mu;
        s_mu[tid] = mu;
        s_rs[tid] = rsqrtf(var + 1e-5f);
        int r = (tid < rows) ? tid : rows - 1;
        s_gp[tid] = gp0 + r;
        int slot = g_list[e * TOKENS + loc0 + r];
        s_slot[tid] = slot;
        s_w[tid] = (tid < rows) ? g_wk[slot] : 0.f;
    }
    __syncthreads();

    // A path: LDG -> LN transform -> tf32 -> STS (2-stage)
    int arow = tid >> 2, kg = tid & 3;
    int agp = s_gp[arow];
    float mu = s_mu[arow], rs = s_rs[arow];
    const float* aP = g_hbuf + (size_t)agp * HID + kbase + kg * 8;
    const float* gP = ln_g + (size_t)e * HID + kbase + kg * 8;
    const float* lP = ln_b + (size_t)e * HID + kbase + kg * 8;
    uint32_t aDst = dynb + (uint32_t)((arow * ASTR2 + kg * 8) * 4);

    // B path: base-pointer addressing
    const float* pB0 = W2 + (size_t)e * HID * DIM + (size_t)kbase * DIM + n0 +
                       (size_t)(tid >> 5) * DIM + (tid & 31) * 4;
    uint32_t dB0 = dynb + (uint32_t)(2 * ABY2 + (tid >> 5) * (BSTR * 4) + (tid & 31) * 16);

    float d[2][4][4];
#pragma unroll
    for (int i = 0; i < 2; i++)
#pragma unroll
        for (int j = 0; j < 4; j++)
#pragma unroll
            for (int c = 0; c < 4; c++) d[i][j][c] = 0.f;

    const int S = HID / KC / SPLITK;   // 32
    float4 av0, av1, gv0, gv1, lv0, lv1;
    av0 = *(const float4*)(aP);     av1 = *(const float4*)(aP + 4);
    gv0 = *(const float4*)(gP);     gv1 = *(const float4*)(gP + 4);
    lv0 = *(const float4*)(lP);     lv1 = *(const float4*)(lP + 4);
#pragma unroll
    for (int ps = 0; ps < 2; ps++) {
#pragma unroll
        for (int i = 0; i < 4; i++)
            cpa16(dB0 + ps * BSTAGE + i * (8 * BSTR * 4), pB0 + (size_t)(ps * KC + 8 * i) * DIM);
        CP_COMMIT();
    }
    {
        float t0 = tf32f((av0.x - mu) * rs * gv0.x + lv0.x);
        float t1 = tf32f((av0.y - mu) * rs * gv0.y + lv0.y);
        float t2 = tf32f((av0.z - mu) * rs * gv0.z + lv0.z);
        float t3 = tf32f((av0.w - mu) * rs * gv0.w + lv0.w);
        float t4 = tf32f((av1.x - mu) * rs * gv1.x + lv1.x);
        float t5 = tf32f((av1.y - mu) * rs * gv1.y + lv1.y);
        float t6 = tf32f((av1.z - mu) * rs * gv1.z + lv1.z);
        float t7 = tf32f((av1.w - mu) * rs * gv1.w + lv1.w);
        sts128(aDst, t0, t1, t2, t3);
        sts128(aDst + 16, t4, t5, t6, t7);
    }
    av0 = *(const float4*)(aP + KC);     av1 = *(const float4*)(aP + KC + 4);
    gv0 = *(const float4*)(gP + KC);     gv1 = *(const float4*)(gP + KC + 4);
    lv0 = *(const float4*)(lP + KC);     lv1 = *(const float4*)(lP + KC + 4);
    CP_WAIT1();
    __syncthreads();

    int st3 = 0, si3 = 2;
    for (int s = 0; s < S; s++) {
        if (s + 1 < S) {
            float t0 = tf32f((av0.x - mu) * rs * gv0.x + lv0.x);
            float t1 = tf32f((av0.y - mu) * rs * gv0.y + lv0.y);
            float t2 = tf32f((av0.z - mu) * rs * gv0.z + lv0.z);
            float t3 = tf32f((av0.w - mu) * rs * gv0.w + lv0.w);
            float t4 = tf32f((av1.x - mu) * rs * gv1.x + lv1.x);
            float t5 = tf32f((av1.y - mu) * rs * gv1.y + lv1.y);
            float t6 = tf32f((av1.z - mu) * rs * gv1.z + lv1.z);
            float t7 = tf32f((av1.w - mu) * rs * gv1.w + lv1.w);
            uint32_t ad = aDst + (uint32_t)(((s + 1) & 1) * ABY2);
            sts128(ad, t0, t1, t2, t3);
            sts128(ad + 16, t4, t5, t6, t7);
        }
        if (s + 2 < S) {
            int k0 = (s + 2) * KC;
            av0 = *(const float4*)(aP + k0);     av1 = *(const float4*)(aP + k0 + 4);
            gv0 = *(const float4*)(gP + k0);     gv1 = *(const float4*)(gP + k0 + 4);
            lv0 = *(const float4*)(lP + k0);     lv1 = *(const float4*)(lP + k0 + 4);
#pragma unroll
            for (int i = 0; i < 4; i++)
                cpa16(dB0 + si3 * BSTAGE + i * (8 * BSTR * 4), pB0 + (size_t)k0 * DIM + (size_t)(8 * i) * DIM);
        }
        CP_COMMIT();
        const float* Ab = dsm + (s & 1) * (ABY2 / 4);
        const float* Bb = dsm + (2 * ABY2) / 4 + st3 * (BSTAGE / 4);
#pragma unroll
        for (int k8 = 0; k8 < KC; k8 += 8) {
            uint32_t af[2][4], bf[4][2];
#pragma unroll
            for (int mf = 0; mf < 2; mf++) {
                const float* ap = Ab + (wm * 32 + mf * 16 + g) * ASTR2 + k8 + tg;
                af[mf][0] = __float_as_uint(ap[0]);
                af[mf][1] = __float_as_uint(ap[8 * ASTR2]);
                af[mf][2] = __float_as_uint(ap[4]);
                af[mf][3] = __float_as_uint(ap[8 * ASTR2 + 4]);
            }
#pragma unroll
            for (int nf = 0; nf < 4; nf++) {
                const float* bp = Bb + (k8 + tg) * BSTR + wn * 32 + nf * 8 + g;
                bf[nf][0] = tf32r(bp[0]);
                bf[nf][1] = tf32r(bp[4 * BSTR]);
            }
#pragma unroll
            for (int mf = 0; mf < 2; mf++)
#pragma unroll
                for (int nf = 0; nf < 4; nf++)
                    mma8(d[mf][nf], af[mf], bf[nf]);
        }
        st3 = (st3 == 2) ? 0 : st3 + 1;
        si3 = (si3 == 2) ? 0 : si3 + 1;
        CP_WAIT1();
        __syncthreads();
    }

    const float* brow = b2 + (size_t)e * DIM + n0;
    float bias[4][2];
#pragma unroll
    for (int nf = 0; nf < 4; nf++) {
        if (ks == 0) {
            int n = wn * 32 + nf * 8 + tg * 2;
            bias[nf][0] = brow[n];
            bias[nf][1] = brow[n + 1];
        } else {
            bias[nf][0] = 0.f;
            bias[nf][1] = 0.f;
        }
    }
#pragma unroll
    for (int mf = 0; mf < 2; mf++) {
#pragma unroll
        for (int h = 0; h < 2; h++) {
            int lr = wm * 32 + mf * 16 + g + 8 * h;
            if (lr >= rows) continue;
            int slot = s_slot[lr];
            float w = s_w[lr];
            float* orow = out + (size_t)(slot >> 1) * DIM + n0 + wn * 32 + tg * 2;
#pragma unroll
            for (int nf = 0; nf < 4; nf++) {
                float v0 = (d[mf][nf][2 * h + 0] + bias[nf][0]) * w;
                float v1 = (d[mf][nf][2 * h + 1] + bias[nf][1]) * w;
                redadd(orow + nf * 8, v0);
                redadd(orow + nf * 8 + 1, v1);
            }
        }
    }
}

extern "C" void kernel_launch(void* const* d_in, const int* in_sizes, int n_in,
                              void* d_out, int out_size) {
    const float* x    = (const float*)d_in[0];
    const float* Wg   = (const float*)d_in[1];
    const float* W1   = (const float*)d_in[2];
    const float* b1   = (const float*)d_in[3];
    const float* ln_g = (const float*)d_in[4];
    const float* ln_b = (const float*)d_in[5];
    const float* W2   = (const float*)d_in[6];
    const float* b2   = (const float*)d_in[7];
    float* out = (float*)d_out;

    cudaFuncSetAttribute(gemm1_kernel, cudaFuncAttributeMaxDynamicSharedMemorySize, 3 * SBYTES);
    cudaFuncSetAttribute(gemm2_kernel, cudaFuncAttributeMaxDynamicSharedMemorySize, SMEM2);

    void* cntp = nullptr;
    cudaGetSymbolAddress(&cntp, g_cnt);
    cudaMemsetAsync(cntp, 0, NEXP * sizeof(int));
    cudaMemsetAsync(out, 0, (size_t)out_size * sizeof(float));
    route_kernel<<<TOKENS / 8, 256>>>(x, Wg);
    gemm1_kernel<<<dim3(NB1, MAXT), 256, 3 * SBYTES>>>(W1, b1);
    gemm2_kernel<<<dim3(NB2, MAXT2, SPLITK), 256, SMEM2>>>(W2, b2, ln_g, ln_b, out);
}

// round 16
// speedup vs baseline: 1.4215x; 1.4215x over previous
#include <cuda_runtime.h>
#include <cstdint>
#include <math.h>

#define TOKENS 2048
#define DIM    512
#define NEXP   16
#define HID    2048
#define NSLOTS (TOKENS*2)
#define TMT    128
#define KC     32
#define MAXT   48
#define TM2    64
#define MAXT2  80
#define SPLITK 2
#define NB1    (HID/128)   // 16
#define NB2    (DIM/128)   // 4
// gemm1 (cp.async A, permuted layout)
#define ASTR   40
#define BSTR   136
#define ABYTES (128*ASTR*4)              // 20480
#define SBYTES (ABYTES + KC*BSTR*4)      // 37888
#define SFLOAT (SBYTES/4)
#define AFLOAT (ABYTES/4)
// gemm2 (reg A path, natural layout)
#define ASTR2   36
#define ABY2    (64*ASTR2*4)             // 9216
#define BSTAGE  (KC*BSTR*4)              // 17408
#define SMEM2   (2*ABY2 + 3*BSTAGE)      // 70656

// ---------------- device scratch ----------------
__device__ int   g_cnt[NEXP];
__device__ int   g_list[NEXP*TOKENS];
__device__ float g_wk[NSLOTS];
__device__ float g_psum[NSLOTS*NB1], g_psq[NSLOTS*NB1];
__device__ float g_xr[(size_t)TOKENS*DIM];
__device__ float g_hbuf[(size_t)NSLOTS*HID];

// ---------------- helpers ----------------
__device__ __forceinline__ uint32_t smem_u32(const void* p) {
    uint32_t a;
    asm("{ .reg .u64 t; cvta.to.shared.u64 t, %1; cvt.u32.u64 %0, t; }" : "=r"(a) : "l"(p));
    return a;
}
__device__ __forceinline__ uint32_t tf32r(float x) {
    uint32_t r; asm("cvt.rna.tf32.f32 %0, %1;" : "=r"(r) : "f"(x)); return r;
}
__device__ __forceinline__ float tf32f(float x) { return __uint_as_float(tf32r(x)); }
__device__ __forceinline__ void mma8(float* d, const uint32_t* a, const uint32_t* b) {
    asm("mma.sync.aligned.m16n8k8.row.col.f32.tf32.tf32.f32 "
        "{%0,%1,%2,%3}, {%4,%5,%6,%7}, {%8,%9}, {%0,%1,%2,%3};"
        : "+f"(d[0]), "+f"(d[1]), "+f"(d[2]), "+f"(d[3])
        : "r"(a[0]), "r"(a[1]), "r"(a[2]), "r"(a[3]), "r"(b[0]), "r"(b[1]));
}
__device__ __forceinline__ void cpa16(uint32_t dst, const float* src) {
    asm volatile("cp.async.cg.shared.global [%0], [%1], 16;" :: "r"(dst), "l"(src));
}
#define CP_COMMIT() asm volatile("cp.async.commit_group;" ::: "memory")
#define CP_WAIT1()  asm volatile("cp.async.wait_group 1;" ::: "memory")
__device__ __forceinline__ void sts128(uint32_t a, float x, float y, float z, float w) {
    asm volatile("st.shared.v4.f32 [%0], {%1,%2,%3,%4};" :: "r"(a), "f"(x), "f"(y), "f"(z), "f"(w));
}
__device__ __forceinline__ void redadd(float* p, float v) {
    asm volatile("red.global.add.f32 [%0], %1;" :: "l"(p), "f"(v) : "memory");
}
__device__ __forceinline__ float silu(float v) { return v / (1.f + __expf(-v)); }

// tile -> (expert, gp0 global, loc0 within-expert, rows); returns false past end
__device__ __forceinline__ bool tilemap(int tile, int TM, int& e, int& gp0, int& loc0, int& rows) {
    int a = 0, tt = tile;
    bool ok = false;
#pragma unroll
    for (int ee = 0; ee < NEXP; ee++) {
        int c = g_cnt[ee];
        int nt = (c + TM - 1) / TM;
        if (!ok) {
            if (tt < nt) {
                e = ee; loc0 = tt * TM; gp0 = a + loc0;
                rows = min(TM, c - loc0); ok = true;
            } else tt -= nt;
        }
        a += c;
    }
    return ok;
}

// ---------------- route: 32-lane gate GEMV + top-2 + softmax + permuted tf32 x ----------------
__global__ __launch_bounds__(256) void route_kernel(const float* __restrict__ x,
                                                    const float* __restrict__ Wg) {
    int t = (blockIdx.x * blockDim.x + threadIdx.x) >> 5;
    int lane = threadIdx.x & 31;
    if (t >= TOKENS) return;
    const float* xr = x + (size_t)t * DIM;
    int ex = lane & 15;
    int off = (lane >> 4) * 256;
    const float* xh = xr + off;
    const float* Wh = Wg + (size_t)off * NEXP + ex;
    float a0 = 0.f, a1 = 0.f, a2 = 0.f, a3 = 0.f;
#pragma unroll 16
    for (int d = 0; d < 256; d += 4) {
        a0 = fmaf(xh[d + 0], Wh[(d + 0) * NEXP], a0);
        a1 = fmaf(xh[d + 1], Wh[(d + 1) * NEXP], a1);
        a2 = fmaf(xh[d + 2], Wh[(d + 2) * NEXP], a2);
        a3 = fmaf(xh[d + 3], Wh[(d + 3) * NEXP], a3);
    }
    float acc = (a0 + a1) + (a2 + a3);
    acc += __shfl_down_sync(0xffffffffu, acc, 16);
    float v0 = -1e30f, v1 = -1e30f;
    int i0 = 0, i1 = 0;
#pragma unroll
    for (int i = 0; i < NEXP; i++) {
        float vi = __shfl_sync(0xffffffffu, acc, i);
        if (vi > v0)      { v1 = v0; i1 = i0; v0 = vi; i0 = i; }
        else if (vi > v1) { v1 = vi; i1 = i; }
    }
    if (lane == 0) {
        float e1 = __expf(v1 - v0);
        float s  = 1.f + e1;
        g_wk[t * 2 + 0] = 1.f / s;
        g_wk[t * 2 + 1] = e1 / s;
        int p0 = atomicAdd(&g_cnt[i0], 1);
        g_list[i0 * TOKENS + p0] = t * 2 + 0;
        int p1 = atomicAdd(&g_cnt[i1], 1);
        g_list[i1 * TOKENS + p1] = t * 2 + 1;
    }
#pragma unroll
    for (int j = 0; j < 2; j++) {
        int G = lane * 2 + j;
        const float4* s = (const float4*)(xr + G * 8);
        float4 u = s[0], v = s[1];
        float4 o0 = make_float4(tf32f(u.x), tf32f(v.x), tf32f(u.y), tf32f(v.y));
        float4 o1 = make_float4(tf32f(u.z), tf32f(v.z), tf32f(u.w), tf32f(v.w));
        float4* dd = (float4*)(g_xr + (size_t)t * DIM + G * 8);
        dd[0] = o0; dd[1] = o1;
    }
}

// ---------------- GEMM1: h = silu(xr @ W1 + b1), fused LN partials ----------------
__global__ __launch_bounds__(256, 2) void gemm1_kernel(const float* __restrict__ W1,
                                                       const float* __restrict__ b1) {
    extern __shared__ float dsm[];
    __shared__ int s_tok[TMT];
    int e, gp0, loc0, rows;
    if (!tilemap(blockIdx.y, TMT, e, gp0, loc0, rows)) return;
    int n0 = blockIdx.x * 128;
    int tid = threadIdx.x, lane = tid & 31, wid = tid >> 5;
    int g = lane >> 2, tg = lane & 3;
    int wm = wid & 1, wn = wid >> 1;
    uint32_t dynb = smem_u32(dsm);

    if (tid < TMT) {
        int r = (tid < rows) ? tid : rows - 1;
        s_tok[tid] = g_list[e * TOKENS + loc0 + r] >> 1;
    }
    __syncthreads();

    const float* pA[4];
    uint32_t dA[4];
    const float* pB[4];
    uint32_t dB[4];
    const float* Wb = W1 + (size_t)e * DIM * HID + n0;
#pragma unroll
    for (int i = 0; i < 4; i++) {
        int c = tid + 256 * i;
        int row = c >> 3, fo = (c & 7) * 4;
        pA[i] = g_xr + (size_t)s_tok[row] * DIM + fo;
        dA[i] = dynb + (uint32_t)(row * (ASTR * 4) + fo * 4);
        int kr = c >> 5, nc = (c & 31) * 4;
        pB[i] = Wb + (size_t)kr * HID + nc;
        dB[i] = dynb + (uint32_t)(ABYTES + kr * (BSTR * 4) + nc * 4);
    }

    float d[4][4][4];
#pragma unroll
    for (int i = 0; i < 4; i++)
#pragma unroll
        for (int j = 0; j < 4; j++)
#pragma unroll
            for (int c = 0; c < 4; c++) d[i][j][c] = 0.f;

    const int S = DIM / KC;   // 16
#pragma unroll
    for (int ps = 0; ps < 2; ps++) {
#pragma unroll
        for (int i = 0; i < 4; i++) {
            cpa16(dA[i] + ps * SBYTES, pA[i] + ps * KC);
            cpa16(dB[i] + ps * SBYTES, pB[i] + (size_t)ps * KC * HID);
        }
        CP_COMMIT();
    }

    int st = 0, si = 2;
    for (int s = 0; s < S; s++) {
        CP_WAIT1();
        __syncthreads();
        if (s + 2 < S) {
            int k0 = (s + 2) * KC;
#pragma unroll
            for (int i = 0; i < 4; i++) {
                cpa16(dA[i] + si * SBYTES, pA[i] + k0);
                cpa16(dB[i] + si * SBYTES, pB[i] + (size_t)k0 * HID);
            }
        }
        CP_COMMIT();
        const float* Ab = dsm + st * SFLOAT;
        const float* Bb = Ab + AFLOAT;
#pragma unroll
        for (int k8 = 0; k8 < KC; k8 += 8) {
            uint32_t af[4][4], bf[4][2];
#pragma unroll
            for (int mf = 0; mf < 4; mf++) {
                const float* ap = Ab + (wm * 64 + mf * 16 + g) * ASTR + k8 + 2 * tg;
                float2 lo = *(const float2*)ap;
                float2 hi = *(const float2*)(ap + 8 * ASTR);
                af[mf][0] = __float_as_uint(lo.x);
                af[mf][1] = __float_as_uint(hi.x);
                af[mf][2] = __float_as_uint(lo.y);
                af[mf][3] = __float_as_uint(hi.y);
            }
#pragma unroll
            for (int nf = 0; nf < 4; nf++) {
                const float* bp = Bb + (k8 + tg) * BSTR + wn * 32 + nf * 8 + g;
                bf[nf][0] = tf32r(bp[0]);
                bf[nf][1] = tf32r(bp[4 * BSTR]);
            }
#pragma unroll
            for (int mf = 0; mf < 4; mf++)
#pragma unroll
                for (int nf = 0; nf < 4; nf++)
                    mma8(d[mf][nf], af[mf], bf[nf]);
        }
        st = (st == 2) ? 0 : st + 1;
        si = (si == 2) ? 0 : si + 1;
    }
    __syncthreads();
    float* s_sum = dsm;
    float* s_sq  = dsm + 512;

    const float* brow = b1 + (size_t)e * HID + n0;
    float bias[4][2];
#pragma unroll
    for (int nf = 0; nf < 4; nf++) {
        int n = wn * 32 + nf * 8 + tg * 2;
        bias[nf][0] = brow[n];
        bias[nf][1] = brow[n + 1];
    }
#pragma unroll
    for (int mf = 0; mf < 4; mf++) {
#pragma unroll
        for (int h = 0; h < 2; h++) {
            int lr = wm * 64 + mf * 16 + g + 8 * h;
            bool val = (lr < rows);
            int gp = gp0 + lr;
            float ss = 0.f, qq = 0.f;
            float* hrow = g_hbuf + (size_t)gp * HID + n0;
#pragma unroll
            for (int nf = 0; nf < 4; nf++) {
                float v0 = silu(d[mf][nf][2 * h + 0] + bias[nf][0]);
                float v1 = silu(d[mf][nf][2 * h + 1] + bias[nf][1]);
                ss += v0 + v1;
                qq += v0 * v0 + v1 * v1;
                if (val) {
                    *(float2*)(hrow + wn * 32 + nf * 8 + tg * 2) = make_float2(v0, v1);
                }
            }
            ss += __shfl_xor_sync(0xffffffffu, ss, 1);
            ss += __shfl_xor_sync(0xffffffffu, ss, 2);
            qq += __shfl_xor_sync(0xffffffffu, qq, 1);
            qq += __shfl_xor_sync(0xffffffffu, qq, 2);
            if (tg == 0) { s_sum[wn * TMT + lr] = ss; s_sq[wn * TMT + lr] = qq; }
        }
    }
    __syncthreads();
    if (tid < TMT && tid < rows) {
        float ts = s_sum[tid] + s_sum[TMT + tid] + s_sum[2 * TMT + tid] + s_sum[3 * TMT + tid];
        float tq = s_sq[tid] + s_sq[TMT + tid] + s_sq[2 * TMT + tid] + s_sq[3 * TMT + tid];
        g_psum[(size_t)(gp0 + tid) * NB1 + blockIdx.x] = ts;
        g_psq [(size_t)(gp0 + tid) * NB1 + blockIdx.x] = tq;
    }
}

// ---------------- GEMM2 (TM=64, split-K=2): out += w * ((LN(h)g+b) @ W2 [+ b2]) ----------------
__global__ __launch_bounds__(256, 2) void gemm2_kernel(const float* __restrict__ W2,
                                                       const float* __restrict__ b2,
                                                       const float* __restrict__ ln_g,
                                                       const float* __restrict__ ln_b,
                                                       float* __restrict__ out) {
    extern __shared__ float dsm[];
    __shared__ int s_gp[TM2], s_slot[TM2];
    __shared__ float s_w[TM2], s_mu[TM2], s_rs[TM2];
    __shared__ float s_red[512];
    int e, gp0, loc0, rows;
    if (!tilemap(blockIdx.y, TM2, e, gp0, loc0, rows)) return;
    int n0 = blockIdx.x * 128;
    int ks = blockIdx.z;
    int kbase = ks * (HID / SPLITK);
    int tid = threadIdx.x, lane = tid & 31, wid = tid >> 5;
    int g = lane >> 2, tg = lane & 3;
    int wm = wid & 1, wn = wid >> 1;
    uint32_t dynb = smem_u32(dsm);

    // inline LN stats
    {
        int row = tid >> 2, part = tid & 3;
        int r = (row < rows) ? row : rows - 1;
        int gp = gp0 + r;
        const float* pp = g_psum + (size_t)gp * NB1 + part * 4;
        const float* qp = g_psq  + (size_t)gp * NB1 + part * 4;
        s_red[tid] = pp[0] + pp[1] + pp[2] + pp[3];
        s_red[256 + tid] = qp[0] + qp[1] + qp[2] + qp[3];
    }
    __syncthreads();
    if (tid < TM2) {
        float ps = s_red[tid * 4] + s_red[tid * 4 + 1] + s_red[tid * 4 + 2] + s_red[tid * 4 + 3];
        float qs = s_red[256 + tid * 4] + s_red[256 + tid * 4 + 1] +
                   s_red[256 + tid * 4 + 2] + s_red[256 + tid * 4 + 3];
        float mu = ps * (1.f / HID);
        float var = qs * (1.f / HID) - mu * mu;
        s_mu[tid] = mu;
        s_rs[tid] = rsqrtf(var + 1e-5f);
        int r = (tid < rows) ? tid : rows - 1;
        s_gp[tid] = gp0 + r;
        int slot = g_list[e * TOKENS + loc0 + r];
        s_slot[tid] = slot;
        s_w[tid] = (tid < rows) ? g_wk[slot] : 0.f;
    }
    __syncthreads();

    // A path: LDG -> LN transform -> tf32 -> STS (2-stage)
    int arow = tid >> 2, kg = tid & 3;
    int agp = s_gp[arow];
    float mu = s_mu[arow], rs = s_rs[arow];
    const float* aP = g_hbuf + (size_t)agp * HID + kbase + kg * 8;
    const float* gP = ln_g + (size_t)e * HID + kbase + kg * 8;
    const float* lP = ln_b + (size_t)e * HID + kbase + kg * 8;
    uint32_t aDst = dynb + (uint32_t)((arow * ASTR2 + kg * 8) * 4);

    // B path: base-pointer addressing
    const float* pB0 = W2 + (size_t)e * HID * DIM + (size_t)kbase * DIM + n0 +
                       (size_t)(tid >> 5) * DIM + (tid & 31) * 4;
    uint32_t dB0 = dynb + (uint32_t)(2 * ABY2 + (tid >> 5) * (BSTR * 4) + (tid & 31) * 16);

    float d[2][4][4];
#pragma unroll
    for (int i = 0; i < 2; i++)
#pragma unroll
        for (int j = 0; j < 4; j++)
#pragma unroll
            for (int c = 0; c < 4; c++) d[i][j][c] = 0.f;

    const int S = HID / KC / SPLITK;   // 32
    float4 av0, av1, gv0, gv1, lv0, lv1;
    av0 = *(const float4*)(aP);     av1 = *(const float4*)(aP + 4);
    gv0 = *(const float4*)(gP);     gv1 = *(const float4*)(gP + 4);
    lv0 = *(const float4*)(lP);     lv1 = *(const float4*)(lP + 4);
#pragma unroll
    for (int ps = 0; ps < 2; ps++) {
#pragma unroll
        for (int i = 0; i < 4; i++)
            cpa16(dB0 + ps * BSTAGE + i * (8 * BSTR * 4), pB0 + (size_t)(ps * KC + 8 * i) * DIM);
        CP_COMMIT();
    }
    {
        float t0 = tf32f((av0.x - mu) * rs * gv0.x + lv0.x);
        float t1 = tf32f((av0.y - mu) * rs * gv0.y + lv0.y);
        float t2 = tf32f((av0.z - mu) * rs * gv0.z + lv0.z);
        float t3 = tf32f((av0.w - mu) * rs * gv0.w + lv0.w);
        float t4 = tf32f((av1.x - mu) * rs * gv1.x + lv1.x);
        float t5 = tf32f((av1.y - mu) * rs * gv1.y + lv1.y);
        float t6 = tf32f((av1.z - mu) * rs * gv1.z + lv1.z);
        float t7 = tf32f((av1.w - mu) * rs * gv1.w + lv1.w);
        sts128(aDst, t0, t1, t2, t3);
        sts128(aDst + 16, t4, t5, t6, t7);
    }
    av0 = *(const float4*)(aP + KC);     av1 = *(const float4*)(aP + KC + 4);
    gv0 = *(const float4*)(gP + KC);     gv1 = *(const float4*)(gP + KC + 4);
    lv0 = *(const float4*)(lP + KC);     lv1 = *(const float4*)(lP + KC + 4);
    CP_WAIT1();
    __syncthreads();

    int st3 = 0, si3 = 2;
    for (int s = 0; s < S; s++) {
        if (s + 1 < S) {
            float t0 = tf32f((av0.x - mu) * rs * gv0.x + lv0.x);
            float t1 = tf32f((av0.y - mu) * rs * gv0.y + lv0.y);
            float t2 = tf32f((av0.z - mu) * rs * gv0.z + lv0.z);
            float t3 = tf32f((av0.w - mu) * rs * gv0.w + lv0.w);
            float t4 = tf32f((av1.x - mu) * rs * gv1.x + lv1.x);
            float t5 = tf32f((av1.y - mu) * rs * gv1.y + lv1.y);
            float t6 = tf32f((av1.z - mu) * rs * gv1.z + lv1.z);
            float t7 = tf32f((av1.w - mu) * rs * gv1.w + lv1.w);
            uint32_t ad = aDst + (uint32_t)(((s + 1) & 1) * ABY2);
            sts128(ad, t0, t1, t2, t3);
            sts128(ad + 16, t4, t5, t6, t7);
        }
        if (s + 2 < S) {
            int k0 = (s + 2) * KC;
            av0 = *(const float4*)(aP + k0);     av1 = *(const float4*)(aP + k0 + 4);
            gv0 = *(const float4*)(gP + k0);     gv1 = *(const float4*)(gP + k0 + 4);
            lv0 = *(const float4*)(lP + k0);     lv1 = *(const float4*)(lP + k0 + 4);
#pragma unroll
            for (int i = 0; i < 4; i++)
                cpa16(dB0 + si3 * BSTAGE + i * (8 * BSTR * 4), pB0 + (size_t)k0 * DIM + (size_t)(8 * i) * DIM);
        }
        CP_COMMIT();
        const float* Ab = dsm + (s & 1) * (ABY2 / 4);
        const float* Bb = dsm + (2 * ABY2) / 4 + st3 * (BSTAGE / 4);
#pragma unroll
        for (int k8 = 0; k8 < KC; k8 += 8) {
            uint32_t af[2][4], bf[4][2];
#pragma unroll
            for (int mf = 0; mf < 2; mf++) {
                const float* ap = Ab + (wm * 32 + mf * 16 + g) * ASTR2 + k8 + tg;
                af[mf][0] = __float_as_uint(ap[0]);
                af[mf][1] = __float_as_uint(ap[8 * ASTR2]);
                af[mf][2] = __float_as_uint(ap[4]);
                af[mf][3] = __float_as_uint(ap[8 * ASTR2 + 4]);
            }
#pragma unroll
            for (int nf = 0; nf < 4; nf++) {
                const float* bp = Bb + (k8 + tg) * BSTR + wn * 32 + nf * 8 + g;
                bf[nf][0] = tf32r(bp[0]);
                bf[nf][1] = tf32r(bp[4 * BSTR]);
            }
#pragma unroll
            for (int mf = 0; mf < 2; mf++)
#pragma unroll
                for (int nf = 0; nf < 4; nf++)
                    mma8(d[mf][nf], af[mf], bf[nf]);
        }
        st3 = (st3 == 2) ? 0 : st3 + 1;
        si3 = (si3 == 2) ? 0 : si3 + 1;
        CP_WAIT1();
        __syncthreads();
    }

    const float* brow = b2 + (size_t)e * DIM + n0;
    float bias[4][2];
#pragma unroll
    for (int nf = 0; nf < 4; nf++) {
        if (ks == 0) {
            int n = wn * 32 + nf * 8 + tg * 2;
            bias[nf][0] = brow[n];
            bias[nf][1] = brow[n + 1];
        } else {
            bias[nf][0] = 0.f;
            bias[nf][1] = 0.f;
        }
    }
#pragma unroll
    for (int mf = 0; mf < 2; mf++) {
#pragma unroll
        for (int h = 0; h < 2; h++) {
            int lr = wm * 32 + mf * 16 + g + 8 * h;
            if (lr >= rows) continue;
            int slot = s_slot[lr];
            float w = s_w[lr];
            float* orow = out + (size_t)(slot >> 1) * DIM + n0 + wn * 32 + tg * 2;
#pragma unroll
            for (int nf = 0; nf < 4; nf++) {
                float v0 = (d[mf][nf][2 * h + 0] + bias[nf][0]) * w;
                float v1 = (d[mf][nf][2 * h + 1] + bias[nf][1]) * w;
                redadd(orow + nf * 8, v0);
                redadd(orow + nf * 8 + 1, v1);
            }
        }
    }
}

extern "C" void kernel_launch(void* const* d_in, const int* in_sizes, int n_in,
                              void* d_out, int out_size) {
    const float* x    = (const float*)d_in[0];
    const float* Wg   = (const float*)d_in[1];
    const float* W1   = (const float*)d_in[2];
    const float* b1   = (const float*)d_in[3];
    const float* ln_g = (const float*)d_in[4];
    const float* ln_b = (const float*)d_in[5];
    const float* W2   = (const float*)d_in[6];
    const float* b2   = (const float*)d_in[7];
    float* out = (float*)d_out;

    cudaFuncSetAttribute(gemm1_kernel, cudaFuncAttributeMaxDynamicSharedMemorySize, 3 * SBYTES);
    cudaFuncSetAttribute(gemm2_kernel, cudaFuncAttributeMaxDynamicSharedMemorySize, SMEM2);

    void* cntp = nullptr;
    cudaGetSymbolAddress(&cntp, g_cnt);
    cudaMemsetAsync(cntp, 0, NEXP * sizeof(int));
    cudaMemsetAsync(out, 0, (size_t)out_size * sizeof(float));
    route_kernel<<<(TOKENS * 32 + 255) / 256, 256>>>(x, Wg);
    gemm1_kernel<<<dim3(NB1, MAXT), 256, 3 * SBYTES>>>(W1, b1);
    gemm2_kernel<<<dim3(NB2, MAXT2, SPLITK), 256, SMEM2>>>(W2, b2, ln_g, ln_b, out);
}

// round 17
// speedup vs baseline: 1.4772x; 1.0392x over previous
#include <cuda_runtime.h>
#include <cstdint>
#include <math.h>

#define TOKENS 2048
#define DIM    512
#define NEXP   16
#define HID    2048
#define NSLOTS (TOKENS*2)
#define TMT    128
#define KC     32
#define MAXT   48
#define TM2    64
#define MAXT2  80
#define SPLITK 2
#define NB1    (HID/128)   // 16
#define NB2    (DIM/128)   // 4
// gemm1 (cp.async A, permuted layout)
#define ASTR   40
#define BSTR   136
#define ABYTES (128*ASTR*4)              // 20480
#define SBYTES (ABYTES + KC*BSTR*4)      // 37888
#define SFLOAT (SBYTES/4)
#define AFLOAT (ABYTES/4)
// gemm2 (reg A path, natural layout)
#define ASTR2   36
#define ABY2    (64*ASTR2*4)             // 9216
#define BSTAGE  (KC*BSTR*4)              // 17408
#define SMEM2   (2*ABY2 + 3*BSTAGE)      // 70656

// ---------------- device scratch ----------------
__device__ int   g_cnt[NEXP];
__device__ int   g_list[NEXP*TOKENS];
__device__ float g_wk[NSLOTS];
__device__ float g_psum[NSLOTS*NB1], g_psq[NSLOTS*NB1];
__device__ float g_xr[(size_t)TOKENS*DIM];
__device__ float g_hbuf[(size_t)NSLOTS*HID];

// ---------------- helpers ----------------
__device__ __forceinline__ uint32_t smem_u32(const void* p) {
    uint32_t a;
    asm("{ .reg .u64 t; cvta.to.shared.u64 t, %1; cvt.u32.u64 %0, t; }" : "=r"(a) : "l"(p));
    return a;
}
__device__ __forceinline__ uint32_t tf32r(float x) {
    uint32_t r; asm("cvt.rna.tf32.f32 %0, %1;" : "=r"(r) : "f"(x)); return r;
}
__device__ __forceinline__ float tf32f(float x) { return __uint_as_float(tf32r(x)); }
__device__ __forceinline__ void mma8(float* d, const uint32_t* a, const uint32_t* b) {
    asm("mma.sync.aligned.m16n8k8.row.col.f32.tf32.tf32.f32 "
        "{%0,%1,%2,%3}, {%4,%5,%6,%7}, {%8,%9}, {%0,%1,%2,%3};"
        : "+f"(d[0]), "+f"(d[1]), "+f"(d[2]), "+f"(d[3])
        : "r"(a[0]), "r"(a[1]), "r"(a[2]), "r"(a[3]), "r"(b[0]), "r"(b[1]));
}
__device__ __forceinline__ void cpa16(uint32_t dst, const float* src) {
    asm volatile("cp.async.cg.shared.global [%0], [%1], 16;" :: "r"(dst), "l"(src));
}
#define CP_COMMIT() asm volatile("cp.async.commit_group;" ::: "memory")
#define CP_WAIT1()  asm volatile("cp.async.wait_group 1;" ::: "memory")
__device__ __forceinline__ void sts128(uint32_t a, float x, float y, float z, float w) {
    asm volatile("st.shared.v4.f32 [%0], {%1,%2,%3,%4};" :: "r"(a), "f"(x), "f"(y), "f"(z), "f"(w));
}
__device__ __forceinline__ void redadd(float* p, float v) {
    asm volatile("red.global.add.f32 [%0], %1;" :: "l"(p), "f"(v) : "memory");
}
__device__ __forceinline__ float silu(float v) { return v / (1.f + __expf(-v)); }

// tile -> (expert, gp0 global, loc0 within-expert, rows); returns false past end
__device__ __forceinline__ bool tilemap(int tile, int TM, int& e, int& gp0, int& loc0, int& rows) {
    int a = 0, tt = tile;
    bool ok = false;
#pragma unroll
    for (int ee = 0; ee < NEXP; ee++) {
        int c = g_cnt[ee];
        int nt = (c + TM - 1) / TM;
        if (!ok) {
            if (tt < nt) {
                e = ee; loc0 = tt * TM; gp0 = a + loc0;
                rows = min(TM, c - loc0); ok = true;
            } else tt -= nt;
        }
        a += c;
    }
    return ok;
}

// ---------------- route: 2 warps/token gate GEMV + top-2 + softmax + permuted tf32 x ----------------
__global__ __launch_bounds__(256) void route_kernel(const float* __restrict__ x,
                                                    const float* __restrict__ Wg) {
    __shared__ float sL[4][2][16];
    int tid = threadIdx.x, wid = tid >> 5, lane = tid & 31;
    int tb = wid >> 1, h = wid & 1;
    int t = blockIdx.x * 4 + tb;
    const float* xr = x + (size_t)t * DIM;
    // warp h covers dims [h*256, h*256+256); lane groups split 128/128
    int ex = lane & 15;
    int off = h * 256 + (lane >> 4) * 128;
    const float* xh = xr + off;
    const float* Wh = Wg + (size_t)off * NEXP + ex;
    float a0 = 0.f, a1 = 0.f, a2 = 0.f, a3 = 0.f;
#pragma unroll 8
    for (int d = 0; d < 128; d += 4) {
        a0 = fmaf(xh[d + 0], Wh[(d + 0) * NEXP], a0);
        a1 = fmaf(xh[d + 1], Wh[(d + 1) * NEXP], a1);
        a2 = fmaf(xh[d + 2], Wh[(d + 2) * NEXP], a2);
        a3 = fmaf(xh[d + 3], Wh[(d + 3) * NEXP], a3);
    }
    float acc = (a0 + a1) + (a2 + a3);
    acc += __shfl_down_sync(0xffffffffu, acc, 16);
    if (lane < 16) sL[tb][h][lane] = acc;
    // permuted tf32 write: this warp's half = 32 groups of 8; one group per lane
    {
        int G = h * 32 + lane;
        const float4* s = (const float4*)(xr + G * 8);
        float4 u = s[0], v = s[1];
        float4 o0 = make_float4(tf32f(u.x), tf32f(v.x), tf32f(u.y), tf32f(v.y));
        float4 o1 = make_float4(tf32f(u.z), tf32f(v.z), tf32f(u.w), tf32f(v.w));
        float4* dd = (float4*)(g_xr + (size_t)t * DIM + G * 8);
        dd[0] = o0; dd[1] = o1;
    }
    __syncthreads();
    if (h == 0) {
        float acc2 = (lane < 16) ? (sL[tb][0][lane] + sL[tb][1][lane]) : -1e30f;
        float v0 = -1e30f, v1 = -1e30f;
        int i0 = 0, i1 = 0;
#pragma unroll
        for (int i = 0; i < NEXP; i++) {
            float vi = __shfl_sync(0xffffffffu, acc2, i);
            if (vi > v0)      { v1 = v0; i1 = i0; v0 = vi; i0 = i; }
            else if (vi > v1) { v1 = vi; i1 = i; }
        }
        if (lane == 0) {
            float e1 = __expf(v1 - v0);
            float s  = 1.f + e1;
            g_wk[t * 2 + 0] = 1.f / s;
            g_wk[t * 2 + 1] = e1 / s;
            int p0 = atomicAdd(&g_cnt[i0], 1);
            g_list[i0 * TOKENS + p0] = t * 2 + 0;
            int p1 = atomicAdd(&g_cnt[i1], 1);
            g_list[i1 * TOKENS + p1] = t * 2 + 1;
        }
    }
}

// ---------------- GEMM1: h = silu(xr @ W1 + b1), fused LN partials ----------------
__global__ __launch_bounds__(256, 2) void gemm1_kernel(const float* __restrict__ W1,
                                                       const float* __restrict__ b1) {
    extern __shared__ float dsm[];
    __shared__ int s_tok[TMT];
    int e, gp0, loc0, rows;
    if (!tilemap(blockIdx.y, TMT, e, gp0, loc0, rows)) return;
    int n0 = blockIdx.x * 128;
    int tid = threadIdx.x, lane = tid & 31, wid = tid >> 5;
    int g = lane >> 2, tg = lane & 3;
    int wm = wid & 1, wn = wid >> 1;
    uint32_t dynb = smem_u32(dsm);

    if (tid < TMT) {
        int r = (tid < rows) ? tid : rows - 1;
        s_tok[tid] = g_list[e * TOKENS + loc0 + r] >> 1;
    }
    __syncthreads();

    const float* pA[4];
    uint32_t dA[4];
    const float* pB[4];
    uint32_t dB[4];
    const float* Wb = W1 + (size_t)e * DIM * HID + n0;
#pragma unroll
    for (int i = 0; i < 4; i++) {
        int c = tid + 256 * i;
        int row = c >> 3, fo = (c & 7) * 4;
        pA[i] = g_xr + (size_t)s_tok[row] * DIM + fo;
        dA[i] = dynb + (uint32_t)(row * (ASTR * 4) + fo * 4);
        int kr = c >> 5, nc = (c & 31) * 4;
        pB[i] = Wb + (size_t)kr * HID + nc;
        dB[i] = dynb + (uint32_t)(ABYTES + kr * (BSTR * 4) + nc * 4);
    }

    float d[4][4][4];
#pragma unroll
    for (int i = 0; i < 4; i++)
#pragma unroll
        for (int j = 0; j < 4; j++)
#pragma unroll
            for (int c = 0; c < 4; c++) d[i][j][c] = 0.f;

    const int S = DIM / KC;   // 16
#pragma unroll
    for (int ps = 0; ps < 2; ps++) {
#pragma unroll
        for (int i = 0; i < 4; i++) {
            cpa16(dA[i] + ps * SBYTES, pA[i] + ps * KC);
            cpa16(dB[i] + ps * SBYTES, pB[i] + (size_t)ps * KC * HID);
        }
        CP_COMMIT();
    }

    int st = 0, si = 2;
    for (int s = 0; s < S; s++) {
        CP_WAIT1();
        __syncthreads();
        if (s + 2 < S) {
            int k0 = (s + 2) * KC;
#pragma unroll
            for (int i = 0; i < 4; i++) {
                cpa16(dA[i] + si * SBYTES, pA[i] + k0);
                cpa16(dB[i] + si * SBYTES, pB[i] + (size_t)k0 * HID);
            }
        }
        CP_COMMIT();
        const float* Ab = dsm + st * SFLOAT;
        const float* Bb = Ab + AFLOAT;
#pragma unroll
        for (int k8 = 0; k8 < KC; k8 += 8) {
            uint32_t af[4][4], bf[4][2];
#pragma unroll
            for (int mf = 0; mf < 4; mf++) {
                const float* ap = Ab + (wm * 64 + mf * 16 + g) * ASTR + k8 + 2 * tg;
                float2 lo = *(const float2*)ap;
                float2 hi = *(const float2*)(ap + 8 * ASTR);
                af[mf][0] = __float_as_uint(lo.x);
                af[mf][1] = __float_as_uint(hi.x);
                af[mf][2] = __float_as_uint(lo.y);
                af[mf][3] = __float_as_uint(hi.y);
            }
#pragma unroll
            for (int nf = 0; nf < 4; nf++) {
                const float* bp = Bb + (k8 + tg) * BSTR + wn * 32 + nf * 8 + g;
                bf[nf][0] = tf32r(bp[0]);
                bf[nf][1] = tf32r(bp[4 * BSTR]);
            }
#pragma unroll
            for (int mf = 0; mf < 4; mf++)
#pragma unroll
                for (int nf = 0; nf < 4; nf++)
                    mma8(d[mf][nf], af[mf], bf[nf]);
        }
        st = (st == 2) ? 0 : st + 1;
        si = (si == 2) ? 0 : si + 1;
    }
    __syncthreads();
    float* s_sum = dsm;
    float* s_sq  = dsm + 512;

    const float* brow = b1 + (size_t)e * HID + n0;
    float bias[4][2];
#pragma unroll
    for (int nf = 0; nf < 4; nf++) {
        int n = wn * 32 + nf * 8 + tg * 2;
        bias[nf][0] = brow[n];
        bias[nf][1] = brow[n + 1];
    }
#pragma unroll
    for (int mf = 0; mf < 4; mf++) {
#pragma unroll
        for (int h = 0; h < 2; h++) {
            int lr = wm * 64 + mf * 16 + g + 8 * h;
            bool val = (lr < rows);
            int gp = gp0 + lr;
            float ss = 0.f, qq = 0.f;
            float* hrow = g_hbuf + (size_t)gp * HID + n0;
#pragma unroll
            for (int nf = 0; nf < 4; nf++) {
                float v0 = silu(d[mf][nf][2 * h + 0] + bias[nf][0]);
                float v1 = silu(d[mf][nf][2 * h + 1] + bias[nf][1]);
                ss += v0 + v1;
                qq += v0 * v0 + v1 * v1;
                if (val) {
                    *(float2*)(hrow + wn * 32 + nf * 8 + tg * 2) = make_float2(v0, v1);
                }
            }
            ss += __shfl_xor_sync(0xffffffffu, ss, 1);
            ss += __shfl_xor_sync(0xffffffffu, ss, 2);
            qq += __shfl_xor_sync(0xffffffffu, qq, 1);
            qq += __shfl_xor_sync(0xffffffffu, qq, 2);
            if (tg == 0) { s_sum[wn * TMT + lr] = ss; s_sq[wn * TMT + lr] = qq; }
        }
    }
    __syncthreads();
    if (tid < TMT && tid < rows) {
        float ts = s_sum[tid] + s_sum[TMT + tid] + s_sum[2 * TMT + tid] + s_sum[3 * TMT + tid];
        float tq = s_sq[tid] + s_sq[TMT + tid] + s_sq[2 * TMT + tid] + s_sq[3 * TMT + tid];
        g_psum[(size_t)(gp0 + tid) * NB1 + blockIdx.x] = ts;
        g_psq [(size_t)(gp0 + tid) * NB1 + blockIdx.x] = tq;
    }
}

// ---------------- GEMM2 (TM=64, split-K=2): out += w * ((LN(h)g+b) @ W2 [+ b2]) ----------------
__global__ __launch_bounds__(256, 2) void gemm2_kernel(const float* __restrict__ W2,
                                                       const float* __restrict__ b2,
                                                       const float* __restrict__ ln_g,
                                                       const float* __restrict__ ln_b,
                                                       float* __restrict__ out) {
    extern __shared__ float dsm[];
    __shared__ int s_gp[TM2], s_slot[TM2];
    __shared__ float s_w[TM2], s_mu[TM2], s_rs[TM2];
    __shared__ float s_red[512];
    int e, gp0, loc0, rows;
    if (!tilemap(blockIdx.y, TM2, e, gp0, loc0, rows)) return;
    int n0 = blockIdx.x * 128;
    int ks = blockIdx.z;
    int kbase = ks * (HID / SPLITK);
    int tid = threadIdx.x, lane = tid & 31, wid = tid >> 5;
    int g = lane >> 2, tg = lane & 3;
    int wm = wid & 1, wn = wid >> 1;
    uint32_t dynb = smem_u32(dsm);

    // inline LN stats
    {
        int row = tid >> 2, part = tid & 3;
        int r = (row < rows) ? row : rows - 1;
        int gp = gp0 + r;
        const float* pp = g_psum + (size_t)gp * NB1 + part * 4;
        const float* qp = g_psq  + (size_t)gp * NB1 + part * 4;
        s_red[tid] = pp[0] + pp[1] + pp[2] + pp[3];
        s_red[256 + tid] = qp[0] + qp[1] + qp[2] + qp[3];
    }
    __syncthreads();
    if (tid < TM2) {
        float ps = s_red[tid * 4] + s_red[tid * 4 + 1] + s_red[tid * 4 + 2] + s_red[tid * 4 + 3];
        float qs = s_red[256 + tid * 4] + s_red[256 + tid * 4 + 1] +
                   s_red[256 + tid * 4 + 2] + s_red[256 + tid * 4 + 3];
        float mu = ps * (1.f / HID);
        float var = qs * (1.f / HID) - mu * mu;
        s_mu[tid] = mu;
        s_rs[tid] = rsqrtf(var + 1e-5f);
        int r = (tid < rows) ? tid : rows - 1;
        s_gp[tid] = gp0 + r;
        int slot = g_list[e * TOKENS + loc0 + r];
        s_slot[tid] = slot;
        s_w[tid] = (tid < rows) ? g_wk[slot] : 0.f;
    }
    __syncthreads();

    // A path: LDG -> LN transform -> tf32 -> STS (2-stage)
    int arow = tid >> 2, kg = tid & 3;
    int agp = s_gp[arow];
    float mu = s_mu[arow], rs = s_rs[arow];
    const float* aP = g_hbuf + (size_t)agp * HID + kbase + kg * 8;
    const float* gP = ln_g + (size_t)e * HID + kbase + kg * 8;
    const float* lP = ln_b + (size_t)e * HID + kbase + kg * 8;
    uint32_t aDst = dynb + (uint32_t)((arow * ASTR2 + kg * 8) * 4);

    // B path: base-pointer addressing
    const float* pB0 = W2 + (size_t)e * HID * DIM + (size_t)kbase * DIM + n0 +
                       (size_t)(tid >> 5) * DIM + (tid & 31) * 4;
    uint32_t dB0 = dynb + (uint32_t)(2 * ABY2 + (tid >> 5) * (BSTR * 4) + (tid & 31) * 16);

    float d[2][4][4];
#pragma unroll
    for (int i = 0; i < 2; i++)
#pragma unroll
        for (int j = 0; j < 4; j++)
#pragma unroll
            for (int c = 0; c < 4; c++) d[i][j][c] = 0.f;

    const int S = HID / KC / SPLITK;   // 32
    float4 av0, av1, gv0, gv1, lv0, lv1;
    av0 = *(const float4*)(aP);     av1 = *(const float4*)(aP + 4);
    gv0 = *(const float4*)(gP);     gv1 = *(const float4*)(gP + 4);
    lv0 = *(const float4*)(lP);     lv1 = *(const float4*)(lP + 4);
#pragma unroll
    for (int ps = 0; ps < 2; ps++) {
#pragma unroll
        for (int i = 0; i < 4; i++)
            cpa16(dB0 + ps * BSTAGE + i * (8 * BSTR * 4), pB0 + (size_t)(ps * KC + 8 * i) * DIM);
        CP_COMMIT();
    }
    {
        float t0 = tf32f((av0.x - mu) * rs * gv0.x + lv0.x);
        float t1 = tf32f((av0.y - mu) * rs * gv0.y + lv0.y);
        float t2 = tf32f((av0.z - mu) * rs * gv0.z + lv0.z);
        float t3 = tf32f((av0.w - mu) * rs * gv0.w + lv0.w);
        float t4 = tf32f((av1.x - mu) * rs * gv1.x + lv1.x);
        float t5 = tf32f((av1.y - mu) * rs * gv1.y + lv1.y);
        float t6 = tf32f((av1.z - mu) * rs * gv1.z + lv1.z);
        float t7 = tf32f((av1.w - mu) * rs * gv1.w + lv1.w);
        sts128(aDst, t0, t1, t2, t3);
        sts128(aDst + 16, t4, t5, t6, t7);
    }
    av0 = *(const float4*)(aP + KC);     av1 = *(const float4*)(aP + KC + 4);
    gv0 = *(const float4*)(gP + KC);     gv1 = *(const float4*)(gP + KC + 4);
    lv0 = *(const float4*)(lP + KC);     lv1 = *(const float4*)(lP + KC + 4);
    CP_WAIT1();
    __syncthreads();

    int st3 = 0, si3 = 2;
    for (int s = 0; s < S; s++) {
        if (s + 1 < S) {
            float t0 = tf32f((av0.x - mu) * rs * gv0.x + lv0.x);
            float t1 = tf32f((av0.y - mu) * rs * gv0.y + lv0.y);
            float t2 = tf32f((av0.z - mu) * rs * gv0.z + lv0.z);
            float t3 = tf32f((av0.w - mu) * rs * gv0.w + lv0.w);
            float t4 = tf32f((av1.x - mu) * rs * gv1.x + lv1.x);
            float t5 = tf32f((av1.y - mu) * rs * gv1.y + lv1.y);
            float t6 = tf32f((av1.z - mu) * rs * gv1.z + lv1.z);
            float t7 = tf32f((av1.w - mu) * rs * gv1.w + lv1.w);
            uint32_t ad = aDst + (uint32_t)(((s + 1) & 1) * ABY2);
            sts128(ad, t0, t1, t2, t3);
            sts128(ad + 16, t4, t5, t6, t7);
        }
        if (s + 2 < S) {
            int k0 = (s + 2) * KC;
            av0 = *(const float4*)(aP + k0);     av1 = *(const float4*)(aP + k0 + 4);
            gv0 = *(const float4*)(gP + k0);     gv1 = *(const float4*)(gP + k0 + 4);
            lv0 = *(const float4*)(lP + k0);     lv1 = *(const float4*)(lP + k0 + 4);
#pragma unroll
            for (int i = 0; i < 4; i++)
                cpa16(dB0 + si3 * BSTAGE + i * (8 * BSTR * 4), pB0 + (size_t)k0 * DIM + (size_t)(8 * i) * DIM);
        }
        CP_COMMIT();
        const float* Ab = dsm + (s & 1) * (ABY2 / 4);
        const float* Bb = dsm + (2 * ABY2) / 4 + st3 * (BSTAGE / 4);
#pragma unroll
        for (int k8 = 0; k8 < KC; k8 += 8) {
            uint32_t af[2][4], bf[4][2];
#pragma unroll
            for (int mf = 0; mf < 2; mf++) {
                const float* ap = Ab + (wm * 32 + mf * 16 + g) * ASTR2 + k8 + tg;
                af[mf][0] = __float_as_uint(ap[0]);
                af[mf][1] = __float_as_uint(ap[8 * ASTR2]);
                af[mf][2] = __float_as_uint(ap[4]);
                af[mf][3] = __float_as_uint(ap[8 * ASTR2 + 4]);
            }
#pragma unroll
            for (int nf = 0; nf < 4; nf++) {
                const float* bp = Bb + (k8 + tg) * BSTR + wn * 32 + nf * 8 + g;
                bf[nf][0] = tf32r(bp[0]);
                bf[nf][1] = tf32r(bp[4 * BSTR]);
            }
#pragma unroll
            for (int mf = 0; mf < 2; mf++)
#pragma unroll
                for (int nf = 0; nf < 4; nf++)
                    mma8(d[mf][nf], af[mf], bf[nf]);
        }
        st3 = (st3 == 2) ? 0 : st3 + 1;
        si3 = (si3 == 2) ? 0 : si3 + 1;
        CP_WAIT1();
        __syncthreads();
    }

    const float* brow = b2 + (size_t)e * DIM + n0;
    float bias[4][2];
#pragma unroll
    for (int nf = 0; nf < 4; nf++) {
        if (ks == 0) {
            int n = wn * 32 + nf * 8 + tg * 2;
            bias[nf][0] = brow[n];
            bias[nf][1] = brow[n + 1];
        } else {
            bias[nf][0] = 0.f;
            bias[nf][1] = 0.f;
        }
    }
#pragma unroll
    for (int mf = 0; mf < 2; mf++) {
#pragma unroll
        for (int h = 0; h < 2; h++) {
            int lr = wm * 32 + mf * 16 + g + 8 * h;
            if (lr >= rows) continue;
            int slot = s_slot[lr];
            float w = s_w[lr];
            float* orow = out + (size_t)(slot >> 1) * DIM + n0 + wn * 32 + tg * 2;
#pragma unroll
            for (int nf = 0; nf < 4; nf++) {
                float v0 = (d[mf][nf][2 * h + 0] + bias[nf][0]) * w;
                float v1 = (d[mf][nf][2 * h + 1] + bias[nf][1]) * w;
                redadd(orow + nf * 8, v0);
                redadd(orow + nf * 8 + 1, v1);
            }
        }
    }
}

extern "C" void kernel_launch(void* const* d_in, const int* in_sizes, int n_in,
                              void* d_out, int out_size) {
    const float* x    = (const float*)d_in[0];
    const float* Wg   = (const float*)d_in[1];
    const float* W1   = (const float*)d_in[2];
    const float* b1   = (const float*)d_in[3];
    const float* ln_g = (const float*)d_in[4];
    const float* ln_b = (const float*)d_in[5];
    const float* W2   = (const float*)d_in[6];
    const float* b2   = (const float*)d_in[7];
    float* out = (float*)d_out;

    cudaFuncSetAttribute(gemm1_kernel, cudaFuncAttributeMaxDynamicSharedMemorySize, 3 * SBYTES);
    cudaFuncSetAttribute(gemm2_kernel, cudaFuncAttributeMaxDynamicSharedMemorySize, SMEM2);

    void* cntp = nullptr;
    cudaGetSymbolAddress(&cntp, g_cnt);
    cudaMemsetAsync(cntp, 0, NEXP * sizeof(int));
    cudaMemsetAsync(out, 0, (size_t)out_size * sizeof(float));
    route_kernel<<<TOKENS / 4, 256>>>(x, Wg);
    gemm1_kernel<<<dim3(NB1, MAXT), 256, 3 * SBYTES>>>(W1, b1);
    gemm2_kernel<<<dim3(NB2, MAXT2, SPLITK), 256, SMEM2>>>(W2, b2, ln_g, ln_b, out);
}